// round 6
// baseline (speedup 1.0000x reference)
#include <cuda_runtime.h>

// Problem constants
#define B_TOT  2
#define E_TOT  2048
#define N1_TOT 96
#define K_TOT  32
#define CIN    64
#define CB     32
#define COUT   64
#define F_TOT  160          // 2*CIN + CB
#define WCNT   (F_TOT*COUT) // 10240
#define NEG_SLOPE 0.01f
#define LIST_MAX 256        // max edges per (b,k); E[count]=64

// fma on packed f32x2
#define FMA2(acc, v, wgt) \
    asm("fma.rn.f32x2 %0, %1, %2, %0;" : "+l"(acc) : "l"(v), "l"(wgt))

// ---------------------------------------------------------------------------
// Single fused kernel. CTA c owns output row (b = c>>5, k = c&31):
//   out[b,k,:] = sum over edges e with idx2[e]==k of att_e * lat_e
//   lat_e = leaky_relu(s1[b,idx1[e]]*W_top + s2[b,k]*W_mid + bonds[b,e]*W_bot + b_eq)
//   (W* = mean_g W_eq[g]; s2*W_mid constant per CTA -> computed once)
// No atomics, no separate zeroing, no prep kernel.
//
// Wbar paired layout (for LDS.128 + f32x2), float index i = ip*128 + t*4 + slot:
//   holds Wbar[f = 2*ip + (slot>>1)][o = 2*t + (slot&1)]
// Thread t owns output pair {2t, 2t+1}.
// ---------------------------------------------------------------------------
__global__ void __launch_bounds__(1024, 1) fused_kernel(
    const float* __restrict__ sites1,
    const float* __restrict__ sites2,
    const float* __restrict__ bonds,
    const float* __restrict__ W_eq,
    const float* __restrict__ b_eq,
    const float* __restrict__ W_att,
    const float* __restrict__ b_att,
    const int*   __restrict__ idx1,
    const int*   __restrict__ idx2,
    float* __restrict__ out)
{
    extern __shared__ char smem_raw[];
    float* Wsh = (float*)smem_raw;                                  // 10240 f (40960 B)
    unsigned long long* sdup = (unsigned long long*)(Wsh + WCNT);   // 64 u64: s2 dup
    unsigned long long* vdup = sdup + 64;                           // 32 warps * 96 u64
    unsigned long long* psum = vdup + 32 * 96;                      // 32*32 u64
    int* list = (int*)(psum + 32 * 32);                             // LIST_MAX ints
    int* cntp = list + LIST_MAX;

    const int tid  = threadIdx.x;
    const int lane = tid & 31;
    const int w    = tid >> 5;
    const int b    = blockIdx.x >> 5;
    const int k    = blockIdx.x & 31;

    // ---- Phase 1: zero counter, stage Wbar (averaged, paired) + s2 dup ----
    if (tid == 0) *cntp = 0;

    #pragma unroll
    for (int j = 0; j < 10; j++) {
        const int i  = tid + j * 1024;
        const int ip = i >> 7, r = i & 127, t = r >> 2, slot = r & 3;
        const int f  = 2 * ip + (slot >> 1);
        const int o  = 2 * t + (slot & 1);
        const int idx = f * COUT + o;
        Wsh[i] = 0.25f * (W_eq[idx] + W_eq[WCNT + idx]
                        + W_eq[2 * WCNT + idx] + W_eq[3 * WCNT + idx]);
    }
    if (tid < CIN) {
        const unsigned u = __float_as_uint(sites2[(b * K_TOT + k) * CIN + tid]);
        sdup[tid] = ((unsigned long long)u << 32) | (unsigned long long)u;
    }
    __syncthreads();

    // ---- Phase 2: scan idx2 for matching edges; compute c_mid per warp ----
    {
        const int e = tid;
        if (idx2[e] == k) list[atomicAdd(cntp, 1)] = e;
        const int e2 = tid + 1024;
        if (idx2[e2] == k) list[atomicAdd(cntp, 1)] = e2;
    }

    // c_mid = s2 . W_mid (pairs ip=32..63), per-lane output pair {2t,2t+1}
    const ulonglong2* Wq = (const ulonglong2*)Wsh;
    const ulonglong2* sq = (const ulonglong2*)sdup;
    unsigned long long cmA = 0ull, cmB = 0ull;
    #pragma unroll
    for (int i = 0; i < 32; i += 2) {
        const ulonglong2 wqA = Wq[(32 + i) * 32 + lane];
        const ulonglong2 qA  = sq[i];
        FMA2(cmA, qA.x, wqA.x);
        FMA2(cmA, qA.y, wqA.y);
        const ulonglong2 wqB = Wq[(33 + i) * 32 + lane];
        const ulonglong2 qB  = sq[i + 1];
        FMA2(cmB, qB.x, wqB.x);
        FMA2(cmB, qB.y, wqB.y);
    }
    const float cm0 = __uint_as_float((unsigned)(cmA & 0xffffffffull))
                    + __uint_as_float((unsigned)(cmB & 0xffffffffull))
                    + b_eq[2 * lane];
    const float cm1 = __uint_as_float((unsigned)(cmA >> 32))
                    + __uint_as_float((unsigned)(cmB >> 32))
                    + b_eq[2 * lane + 1];

    const float wa0 = W_att[2 * lane];
    const float wa1 = W_att[2 * lane + 1];
    const float ba  = b_att[0];

    __syncthreads();
    const int M = *cntp;

    // ---- Phase 3: process edges, warp w takes list[w], list[w+32], ... ----
    const ulonglong2* vq = (const ulonglong2*)(vdup + w * 96);
    unsigned long long* vst = vdup + w * 96;

    float sum0 = 0.0f, sum1 = 0.0f;

    for (int j = w; j < M; j += 32) {
        const int e  = list[j];
        const int i1 = idx1[e];     // same addr across warp: L1 broadcast

        // Stage v (96 features, duplicated into both f32x2 halves):
        //   [0:64) = sites1[b,i1,:],  [64:96) = bonds[b,e,:]
        {
            const float* s1r = sites1 + (b * N1_TOT + i1) * CIN;
            const float* bdr = bonds  + (b * E_TOT  + e ) * CB;
            const unsigned u0 = __float_as_uint(s1r[lane]);
            const unsigned u1 = __float_as_uint(s1r[lane + 32]);
            const unsigned u2 = __float_as_uint(bdr[lane]);
            vst[lane]      = ((unsigned long long)u0 << 32) | u0;
            vst[lane + 32] = ((unsigned long long)u1 << 32) | u1;
            vst[lane + 64] = ((unsigned long long)u2 << 32) | u2;
        }
        __syncwarp();

        // acc over top (ip 0..31 ~ f 0..63) and bot (ip 64..79 ~ f 128..159)
        unsigned long long a0 = ((unsigned long long)__float_as_uint(cm1) << 32)
                              | (unsigned long long)__float_as_uint(cm0);
        unsigned long long a1 = 0ull;
        #pragma unroll
        for (int i = 0; i < 32; i += 2) {
            const ulonglong2 wqA = Wq[i * 32 + lane];
            const ulonglong2 qA  = vq[i];
            FMA2(a0, qA.x, wqA.x);
            FMA2(a0, qA.y, wqA.y);
            const ulonglong2 wqB = Wq[(i + 1) * 32 + lane];
            const ulonglong2 qB  = vq[i + 1];
            FMA2(a1, qB.x, wqB.x);
            FMA2(a1, qB.y, wqB.y);
        }
        #pragma unroll
        for (int i = 0; i < 16; i += 2) {
            const ulonglong2 wqA = Wq[(64 + i) * 32 + lane];
            const ulonglong2 qA  = vq[32 + i];
            FMA2(a0, qA.x, wqA.x);
            FMA2(a0, qA.y, wqA.y);
            const ulonglong2 wqB = Wq[(65 + i) * 32 + lane];
            const ulonglong2 qB  = vq[33 + i];
            FMA2(a1, qB.x, wqB.x);
            FMA2(a1, qB.y, wqB.y);
        }

        float y0 = __uint_as_float((unsigned)(a0 & 0xffffffffull))
                 + __uint_as_float((unsigned)(a1 & 0xffffffffull));
        float y1 = __uint_as_float((unsigned)(a0 >> 32))
                 + __uint_as_float((unsigned)(a1 >> 32));
        y0 = (y0 > 0.0f) ? y0 : NEG_SLOPE * y0;
        y1 = (y1 > 0.0f) ? y1 : NEG_SLOPE * y1;

        float p = y0 * wa0 + y1 * wa1;
        #pragma unroll
        for (int s = 16; s > 0; s >>= 1)
            p += __shfl_xor_sync(0xffffffffu, p, s);
        const float att = 1.0f / (1.0f + __expf(-(p + ba)));

        sum0 += att * y0;
        sum1 += att * y1;
        __syncwarp();   // protect vdup before next stage
    }

    // ---- Phase 4: combine 32 warps, store output row ----
    psum[w * 32 + lane] = ((unsigned long long)__float_as_uint(sum1) << 32)
                        | (unsigned long long)__float_as_uint(sum0);
    __syncthreads();

    if (w == 0) {
        float t0 = 0.0f, t1 = 0.0f;
        #pragma unroll
        for (int j = 0; j < 32; j++) {
            const unsigned long long pp = psum[j * 32 + lane];
            t0 += __uint_as_float((unsigned)(pp & 0xffffffffull));
            t1 += __uint_as_float((unsigned)(pp >> 32));
        }
        float* dst = out + ((size_t)(b * K_TOT + k)) * COUT + 2 * lane;
        dst[0] = t0;
        dst[1] = t1;
    }
}

// ---------------------------------------------------------------------------
extern "C" void kernel_launch(void* const* d_in, const int* in_sizes, int n_in,
                              void* d_out, int out_size)
{
    const float* sites1 = (const float*)d_in[0];
    const float* sites2 = (const float*)d_in[1];
    const float* bonds  = (const float*)d_in[2];
    const float* W_eq   = (const float*)d_in[3];
    const float* b_eq   = (const float*)d_in[4];
    const float* W_att  = (const float*)d_in[5];
    const float* b_att  = (const float*)d_in[6];
    // d_in[7] = idx2_oh (unused — collapsed analytically)
    const int*   idx1   = (const int*)d_in[8];
    const int*   idx2   = (const int*)d_in[9];
    // d_in[10], d_in[11] = perms1/perms2 (unused — permutations cancel)
    float* out = (float*)d_out;

    const int smem_bytes = WCNT * 4            // Wsh   (40960)
                         + 64 * 8              // sdup  (  512)
                         + 32 * 96 * 8         // vdup  (24576)
                         + 32 * 32 * 8         // psum  ( 8192)
                         + LIST_MAX * 4 + 16;  // list + cnt
    cudaFuncSetAttribute(fused_kernel,
                         cudaFuncAttributeMaxDynamicSharedMemorySize, smem_bytes);

    // One CTA per (b, k) output row: 64 CTAs x 1024 threads. Single launch.
    fused_kernel<<<B_TOT * K_TOT, 1024, smem_bytes>>>(sites1, sites2, bonds,
                                                      W_eq, b_eq, W_att, b_att,
                                                      idx1, idx2, out);
}

// round 7
// speedup vs baseline: 2.3571x; 2.3571x over previous
#include <cuda_runtime.h>

// Problem constants
#define B_TOT  2
#define E_TOT  2048
#define N1_TOT 96
#define K_TOT  32
#define CIN    64
#define CB     32
#define COUT   64
#define F_TOT  160          // 2*CIN + CB
#define NPAIR  80           // F_TOT/2
#define WCNT   (F_TOT*COUT) // 10240
#define NEG_SLOPE 0.01f

#define EPW    8            // edges per warp
#define WPC    4            // warps per CTA
#define EPC    (EPW*WPC)    // 32 edges per CTA
#define GRID_M 128          // 4096 / 32

// fma on packed f32x2
#define FMA2(acc, v, wgt) \
    asm("fma.rn.f32x2 %0, %1, %2, %0;" : "+l"(acc) : "l"(v), "l"(wgt))

// Wbar = mean_g W_eq[g], f-PAIRED layout for one LDS.128 per (ip, thread):
//   float index i = ip*128 + t*4 + slot  ->  Wbar[f = 2*ip + (slot&1)][o = t + 32*(slot>>1)]
// lane t's 16B load at (ip*32+t)*16 yields
//   u64.x = {W[2ip][t],   W[2ip+1][t]}    (output o = t)
//   u64.y = {W[2ip][t+32],W[2ip+1][t+32]} (output o = t+32)
__device__ float g_Wp[WCNT];

// ---------------------------------------------------------------------------
// Prep: Wbar into paired layout + zero d_out. Triggers PDL immediately so the
// main kernel can start its (independent) v-gather while this runs.
// ---------------------------------------------------------------------------
__global__ void prep_kernel(const float* __restrict__ W_eq, float* __restrict__ out) {
#if __CUDA_ARCH__ >= 900
    cudaTriggerProgrammaticLaunchCompletion();
#endif
    int i = blockIdx.x * blockDim.x + threadIdx.x;
    if (i < WCNT) {
        const int ip = i >> 7, r = i & 127, t = r >> 2, slot = r & 3;
        const int f = 2 * ip + (slot & 1);
        const int o = t + 32 * (slot >> 1);
        const int idx = f * COUT + o;
        float s = W_eq[idx] + W_eq[WCNT + idx] + W_eq[2 * WCNT + idx] + W_eq[3 * WCNT + idx];
        g_Wp[i] = 0.25f * s;
    }
    if (i < B_TOT * K_TOT * COUT) out[i] = 0.0f;
}

// ---------------------------------------------------------------------------
// Main: 128 CTAs x 128 threads (4 warps), 1/SM. Warp owns 8 edges.
// Thread t owns outputs {t, t+32}; f32x2 packs feature pairs; v loads are
// LDS.64 broadcasts (no duplication), W loads one LDS.128 per pair-iter.
// ---------------------------------------------------------------------------
__global__ void __launch_bounds__(128, 1) main_kernel(
    const float* __restrict__ sites1,
    const float* __restrict__ sites2,
    const float* __restrict__ bonds,
    const float* __restrict__ b_eq,
    const float* __restrict__ W_att,
    const float* __restrict__ b_att,
    const int*   __restrict__ idx1,
    const int*   __restrict__ idx2,
    float* __restrict__ out)
{
    extern __shared__ float smem[];
    float* Wsh = smem;               // 10240 floats (40960 B)
    float* vsh = smem + WCNT;        // 32 edges * 160 floats (20480 B)

    const int tid  = threadIdx.x;
    const int lane = tid & 31;
    const int w    = tid >> 5;

    // ---- Phase A: gather v (plain floats) — independent of prep ----
    int bb[EPW], k2[EPW];
    #pragma unroll
    for (int j = 0; j < EPW; j++) {
        const int le = w * EPW + j;                // 0..31
        const int ei = blockIdx.x * EPC + le;      // 0..4095
        const int b  = ei >> 11;
        const int e  = ei & (E_TOT - 1);
        bb[j] = b;
        const int i1 = idx1[e];
        const int i2 = idx2[e];
        k2[j] = i2;
        #pragma unroll
        for (int m = 0; m < 5; m++) {
            const int f = lane + 32 * m;           // 0..159
            float v;
            if (f < CIN)            v = sites1[(b * N1_TOT + i1) * CIN + f];
            else if (f < 2 * CIN)   v = sites2[(b * K_TOT  + i2) * CIN + (f - CIN)];
            else                    v = bonds [(b * E_TOT  + e ) * CB  + (f - 2 * CIN)];
            vsh[le * F_TOT + f] = v;
        }
    }

    // ---- Wait for prep (Wbar ready, out zeroed) ----
#if __CUDA_ARCH__ >= 900
    cudaGridDependencySynchronize();
#endif

    // ---- Phase B: stage Wbar (paired layout), straight float4 copy ----
    {
        const float4* src = (const float4*)g_Wp;
        float4*       dst = (float4*)Wsh;
        #pragma unroll
        for (int i = 0; i < 20; i++) dst[i * 128 + tid] = src[i * 128 + tid];
    }
    __syncthreads();

    // ---- Phase C: main loop. 80 pair-iters x 8 edges ----
    const ulonglong2* Wq = (const ulonglong2*)Wsh;
    const float* vb = vsh + (w * EPW) * F_TOT;

    unsigned long long aT[EPW], aU[EPW];
    #pragma unroll
    for (int j = 0; j < EPW; j++) { aT[j] = 0ull; aU[j] = 0ull; }

    #pragma unroll 4
    for (int ip = 0; ip < NPAIR; ip++) {
        const ulonglong2 wq = Wq[ip * 32 + lane];
        #pragma unroll
        for (int j = 0; j < EPW; j++) {
            const unsigned long long vp =
                *(const unsigned long long*)(vb + j * F_TOT + 2 * ip);  // {v[2ip],v[2ip+1]} bcast
            FMA2(aT[j], vp, wq.x);   // output o = t   (even/odd f halves)
            FMA2(aU[j], vp, wq.y);   // output o = t+32
        }
    }

    // ---- Phase D: epilogue ----
    const float beT = b_eq[lane];
    const float beU = b_eq[lane + 32];
    const float waT = W_att[lane];
    const float waU = W_att[lane + 32];
    const float ba  = b_att[0];

    #pragma unroll
    for (int j = 0; j < EPW; j++) {
        float yT = __uint_as_float((unsigned)(aT[j] & 0xffffffffull))
                 + __uint_as_float((unsigned)(aT[j] >> 32)) + beT;
        float yU = __uint_as_float((unsigned)(aU[j] & 0xffffffffull))
                 + __uint_as_float((unsigned)(aU[j] >> 32)) + beU;
        yT = (yT > 0.0f) ? yT : NEG_SLOPE * yT;
        yU = (yU > 0.0f) ? yU : NEG_SLOPE * yU;

        float p = yT * waT + yU * waU;
        #pragma unroll
        for (int s = 16; s > 0; s >>= 1)
            p += __shfl_xor_sync(0xffffffffu, p, s);
        const float att = 1.0f / (1.0f + __expf(-(p + ba)));

        float* dst = out + ((size_t)(bb[j] * K_TOT + k2[j])) * COUT;
        atomicAdd(dst + lane,      att * yT);
        atomicAdd(dst + lane + 32, att * yU);
    }
}

// ---------------------------------------------------------------------------
extern "C" void kernel_launch(void* const* d_in, const int* in_sizes, int n_in,
                              void* d_out, int out_size)
{
    const float* sites1 = (const float*)d_in[0];
    const float* sites2 = (const float*)d_in[1];
    const float* bonds  = (const float*)d_in[2];
    const float* W_eq   = (const float*)d_in[3];
    const float* b_eq   = (const float*)d_in[4];
    const float* W_att  = (const float*)d_in[5];
    const float* b_att  = (const float*)d_in[6];
    // d_in[7] = idx2_oh (unused — collapsed analytically)
    const int*   idx1   = (const int*)d_in[8];
    const int*   idx2   = (const int*)d_in[9];
    // d_in[10], d_in[11] = perms1/perms2 (unused — permutations cancel)
    float* out = (float*)d_out;

    const int smem_bytes = WCNT * 4 + EPC * F_TOT * 4;   // 40960 + 20480
    cudaFuncSetAttribute(main_kernel,
                         cudaFuncAttributeMaxDynamicSharedMemorySize, smem_bytes);

    // prep on stream 0
    {
        cudaLaunchConfig_t cfg = {};
        cfg.gridDim  = dim3(40);
        cfg.blockDim = dim3(256);
        cfg.dynamicSmemBytes = 0;
        cfg.stream = 0;
        cudaLaunchKernelEx(&cfg, prep_kernel, W_eq, out);
    }

    // main on stream 0 with programmatic dependent launch (overlaps v-gather
    // with prep; cudaGridDependencySynchronize guards Wbar/out consumption)
    {
        cudaLaunchConfig_t cfg = {};
        cfg.gridDim  = dim3(GRID_M);
        cfg.blockDim = dim3(WPC * 32);
        cfg.dynamicSmemBytes = smem_bytes;
        cfg.stream = 0;
        cudaLaunchAttribute at[1];
        at[0].id = cudaLaunchAttributeProgrammaticStreamSerialization;
        at[0].val.programmaticStreamSerializationAllowed = 1;
        cfg.attrs = at;
        cfg.numAttrs = 1;
        cudaLaunchKernelEx(&cfg, main_kernel, sites1, sites2, bonds,
                           b_eq, W_att, b_att, idx1, idx2, out);
    }
}

// round 8
// speedup vs baseline: 2.3642x; 1.0030x over previous
#include <cuda_runtime.h>

// Problem constants
#define B_TOT  2
#define E_TOT  2048
#define N1_TOT 96
#define K_TOT  32
#define CIN    64
#define CB     32
#define COUT   64
#define F_TOT  160          // 2*CIN + CB
#define NPAIR  80           // F_TOT/2
#define WCNT   (F_TOT*COUT) // 10240
#define NEG_SLOPE 0.01f

#define EPW    4            // edges per warp
#define WPC    8            // warps per CTA
#define EPC    (EPW*WPC)    // 32 edges per CTA
#define GRID_M 128          // 4096 / 32

// fma on packed f32x2
#define FMA2(acc, v, wgt) \
    asm("fma.rn.f32x2 %0, %1, %2, %0;" : "+l"(acc) : "l"(v), "l"(wgt))

// Wbar = mean_g W_eq[g], f-PAIRED layout for one LDS.128 per (ip, thread):
//   float index i = ip*128 + t*4 + slot  ->  Wbar[f = 2*ip + (slot&1)][o = t + 32*(slot>>1)]
// lane t's 16B load at (ip*32+t)*16 yields
//   u64.x = {W[2ip][t],   W[2ip+1][t]}    (output o = t)
//   u64.y = {W[2ip][t+32],W[2ip+1][t+32]} (output o = t+32)
__device__ float g_Wp[WCNT];

// ---------------------------------------------------------------------------
// Prep: Wbar into paired layout + zero d_out. Triggers PDL completion early so
// the main kernel's independent v-gather overlaps with this.
// ---------------------------------------------------------------------------
__global__ void prep_kernel(const float* __restrict__ W_eq, float* __restrict__ out) {
#if __CUDA_ARCH__ >= 900
    cudaTriggerProgrammaticLaunchCompletion();
#endif
    int i = blockIdx.x * blockDim.x + threadIdx.x;
    if (i < WCNT) {
        const int ip = i >> 7, r = i & 127, t = r >> 2, slot = r & 3;
        const int f = 2 * ip + (slot & 1);
        const int o = t + 32 * (slot >> 1);
        const int idx = f * COUT + o;
        float s = W_eq[idx] + W_eq[WCNT + idx] + W_eq[2 * WCNT + idx] + W_eq[3 * WCNT + idx];
        g_Wp[i] = 0.25f * s;
    }
    if (i < B_TOT * K_TOT * COUT) out[i] = 0.0f;
}

// ---------------------------------------------------------------------------
// Main: 128 CTAs x 256 threads (8 warps/SM = 2 per SMSP). Warp owns 4 edges.
// Thread t owns outputs {t, t+32}; f32x2 packs feature pairs; v loads are
// LDS.64 broadcasts; W loads one LDS.128 per pair-iter.
// ---------------------------------------------------------------------------
__global__ void __launch_bounds__(256, 1) main_kernel(
    const float* __restrict__ sites1,
    const float* __restrict__ sites2,
    const float* __restrict__ bonds,
    const float* __restrict__ b_eq,
    const float* __restrict__ W_att,
    const float* __restrict__ b_att,
    const int*   __restrict__ idx1,
    const int*   __restrict__ idx2,
    float* __restrict__ out)
{
    extern __shared__ float smem[];
    float* Wsh = smem;               // 10240 floats (40960 B)
    float* vsh = smem + WCNT;        // 32 edges * 160 floats (20480 B)

    const int tid  = threadIdx.x;
    const int lane = tid & 31;
    const int w    = tid >> 5;

    // ---- Phase A: gather v (plain floats) — independent of prep ----
    int bb[EPW], k2[EPW];
    #pragma unroll
    for (int j = 0; j < EPW; j++) {
        const int le = w * EPW + j;                // 0..31
        const int ei = blockIdx.x * EPC + le;      // 0..4095
        const int b  = ei >> 11;
        const int e  = ei & (E_TOT - 1);
        bb[j] = b;
        const int i1 = idx1[e];
        const int i2 = idx2[e];
        k2[j] = i2;
        #pragma unroll
        for (int m = 0; m < 5; m++) {
            const int f = lane + 32 * m;           // 0..159
            float v;
            if (f < CIN)            v = sites1[(b * N1_TOT + i1) * CIN + f];
            else if (f < 2 * CIN)   v = sites2[(b * K_TOT  + i2) * CIN + (f - CIN)];
            else                    v = bonds [(b * E_TOT  + e ) * CB  + (f - 2 * CIN)];
            vsh[le * F_TOT + f] = v;
        }
    }

    // ---- Wait for prep (Wbar ready, out zeroed) ----
#if __CUDA_ARCH__ >= 900
    cudaGridDependencySynchronize();
#endif

    // ---- Phase B: stage Wbar (paired layout), straight float4 copy ----
    {
        const float4* src = (const float4*)g_Wp;
        float4*       dst = (float4*)Wsh;
        #pragma unroll
        for (int i = 0; i < 10; i++) dst[i * 256 + tid] = src[i * 256 + tid];
    }
    __syncthreads();

    // ---- Phase C: main loop. 80 pair-iters x 4 edges ----
    const ulonglong2* Wq = (const ulonglong2*)Wsh;
    const float* vb = vsh + (w * EPW) * F_TOT;

    unsigned long long aT[EPW], aU[EPW];
    #pragma unroll
    for (int j = 0; j < EPW; j++) { aT[j] = 0ull; aU[j] = 0ull; }

    #pragma unroll 4
    for (int ip = 0; ip < NPAIR; ip++) {
        const ulonglong2 wq = Wq[ip * 32 + lane];
        #pragma unroll
        for (int j = 0; j < EPW; j++) {
            const unsigned long long vp =
                *(const unsigned long long*)(vb + j * F_TOT + 2 * ip);  // {v[2ip],v[2ip+1]} bcast
            FMA2(aT[j], vp, wq.x);   // output o = t
            FMA2(aU[j], vp, wq.y);   // output o = t+32
        }
    }

    // ---- Phase D: epilogue ----
    const float beT = b_eq[lane];
    const float beU = b_eq[lane + 32];
    const float waT = W_att[lane];
    const float waU = W_att[lane + 32];
    const float ba  = b_att[0];

    #pragma unroll
    for (int j = 0; j < EPW; j++) {
        float yT = __uint_as_float((unsigned)(aT[j] & 0xffffffffull))
                 + __uint_as_float((unsigned)(aT[j] >> 32)) + beT;
        float yU = __uint_as_float((unsigned)(aU[j] & 0xffffffffull))
                 + __uint_as_float((unsigned)(aU[j] >> 32)) + beU;
        yT = (yT > 0.0f) ? yT : NEG_SLOPE * yT;
        yU = (yU > 0.0f) ? yU : NEG_SLOPE * yU;

        float p = yT * waT + yU * waU;
        #pragma unroll
        for (int s = 16; s > 0; s >>= 1)
            p += __shfl_xor_sync(0xffffffffu, p, s);
        const float att = 1.0f / (1.0f + __expf(-(p + ba)));

        float* dst = out + ((size_t)(bb[j] * K_TOT + k2[j])) * COUT;
        atomicAdd(dst + lane,      att * yT);
        atomicAdd(dst + lane + 32, att * yU);
    }
}

// ---------------------------------------------------------------------------
extern "C" void kernel_launch(void* const* d_in, const int* in_sizes, int n_in,
                              void* d_out, int out_size)
{
    const float* sites1 = (const float*)d_in[0];
    const float* sites2 = (const float*)d_in[1];
    const float* bonds  = (const float*)d_in[2];
    const float* W_eq   = (const float*)d_in[3];
    const float* b_eq   = (const float*)d_in[4];
    const float* W_att  = (const float*)d_in[5];
    const float* b_att  = (const float*)d_in[6];
    // d_in[7] = idx2_oh (unused — collapsed analytically)
    const int*   idx1   = (const int*)d_in[8];
    const int*   idx2   = (const int*)d_in[9];
    // d_in[10], d_in[11] = perms1/perms2 (unused — permutations cancel)
    float* out = (float*)d_out;

    const int smem_bytes = WCNT * 4 + EPC * F_TOT * 4;   // 40960 + 20480
    cudaFuncSetAttribute(main_kernel,
                         cudaFuncAttributeMaxDynamicSharedMemorySize, smem_bytes);

    // prep on stream 0
    {
        cudaLaunchConfig_t cfg = {};
        cfg.gridDim  = dim3(40);
        cfg.blockDim = dim3(256);
        cfg.dynamicSmemBytes = 0;
        cfg.stream = 0;
        cudaLaunchKernelEx(&cfg, prep_kernel, W_eq, out);
    }

    // main on stream 0 with programmatic dependent launch
    {
        cudaLaunchConfig_t cfg = {};
        cfg.gridDim  = dim3(GRID_M);
        cfg.blockDim = dim3(WPC * 32);
        cfg.dynamicSmemBytes = smem_bytes;
        cfg.stream = 0;
        cudaLaunchAttribute at[1];
        at[0].id = cudaLaunchAttributeProgrammaticStreamSerialization;
        at[0].val.programmaticStreamSerializationAllowed = 1;
        cfg.attrs = at;
        cfg.numAttrs = 1;
        cudaLaunchKernelEx(&cfg, main_kernel, sites1, sites2, bonds,
                           b_eq, W_att, b_att, idx1, idx2, out);
    }
}